// round 17
// baseline (speedup 1.0000x reference)
#include <cuda_runtime.h>
#include <math_constants.h>

// Problem constants
#define BB 64
#define HH 224
#define WW 224
#define CC 196
#define HWP (HH*WW)
#define NEIGH 10

// Round-13 geometry (proven best), 2 barriers/iteration
#define KIT   5             // iterations fused per launch
#define BR    28            // interior rows per band
#define TFY   38            // tile rows = BR + 2*KIT
#define BANDS 8             // 8*28 = 224 exactly
#define RPT   19            // rows per thread (TFY/2)
#define NT    224           // columns (threadIdx.x)
#define NH    2             // halves  (threadIdx.y)
#define NW    7             // warps per half
#define NLAB  5             // packed label regs (4 rows each)
#define DYN_SMEM (3 * TFY * NT * (int)sizeof(float))   // swg+scU+scL: 102144 B

// ---------------- static scratch ----------------
__device__ float         g_wg [BB*HWP];
__device__ float         g_cpU[BB*HWP];
__device__ float         g_cpL[BB*HWP];
__device__ float         g_dA [BB*HWP];
__device__ float         g_dB [BB*HWP];
__device__ unsigned char g_lA [BB*HWP];
__device__ unsigned char g_lB [BB*HWP];
__device__ float         g_minval[BB*CC];
__device__ int           g_minidx[BB*CC];
__device__ int           g_centi [BB*CC*2];

// ---------------- Phase 1a: window min + first argmin ----------------
__global__ void minima_kernel(const float* __restrict__ g) {
    int gw   = (blockIdx.x * blockDim.x + threadIdx.x) >> 5;
    int lane = threadIdx.x & 31;
    if (gw >= BB * CC) return;
    int b = gw / CC, c = gw - b * CC;
    int y0 = 8 + 16 * (c / 14);
    int x0 = 8 + 16 * (c % 14);
    int ymin = max(0, y0 - NEIGH), ymax = min(HH, y0 + NEIGH);
    int xmin = max(0, x0 - NEIGH), xmax = min(WW, x0 + NEIGH);
    int ww = xmax - xmin, n = (ymax - ymin) * ww;
    const float* gb = g + (size_t)b * HWP;

    float bv = CUDART_INF_F;
    int   bi = 0x7fffffff;
    for (int k = lane; k < n; k += 32) {
        int ky = k / ww;
        int f = (ymin + ky) * WW + xmin + (k - ky * ww);
        float v = gb[f];
        if (v < bv || (v == bv && f < bi)) { bv = v; bi = f; }
    }
    #pragma unroll
    for (int off = 16; off; off >>= 1) {
        float ov = __shfl_down_sync(0xffffffffu, bv, off);
        int   oi = __shfl_down_sync(0xffffffffu, bi, off);
        if (ov < bv || (ov == bv && oi < bi)) { bv = ov; bi = oi; }
    }
    if (lane == 0) { g_minval[gw] = bv; g_minidx[gw] = bi; }
}

// ---------------- Phase 1b: occupied-dedup, one warp per batch ----------------
__global__ void resolve_kernel(const float* __restrict__ g, float* __restrict__ out_cents) {
    __shared__ unsigned int occ[(HWP + 31) / 32];
    int b    = blockIdx.x;
    int lane = threadIdx.x;
    for (int i = lane; i < (HWP + 31) / 32; i += 32) occ[i] = 0u;
    __syncwarp();
    const float* gb = g + (size_t)b * HWP;

    for (int c = 0; c < CC; c++) {
        float mv = g_minval[b * CC + c];
        int   mi = g_minidx[b * CC + c];
        int y0c = 8 + 16 * (c / 14);
        int x0c = 8 + 16 * (c % 14);
        bool isocc = (occ[mi >> 5] >> (mi & 31)) & 1u;
        int  chosen = mi;
        bool found  = true;
        if (isocc) {
            found = false;
            int ymin = max(0, y0c - NEIGH), ymax = min(HH, y0c + NEIGH);
            int xmin = max(0, x0c - NEIGH), xmax = min(WW, x0c + NEIGH);
            int wwid = xmax - xmin, n = (ymax - ymin) * wwid;
            for (int base = 0; base < n; base += 32) {
                int k = base + lane;
                bool m = false; int f = 0;
                if (k < n) {
                    int ky = k / wwid;
                    f = (ymin + ky) * WW + xmin + (k - ky * wwid);
                    m = (gb[f] == mv) && !((occ[f >> 5] >> (f & 31)) & 1u);
                }
                unsigned bal = __ballot_sync(0xffffffffu, m);
                if (bal) {
                    chosen = __shfl_sync(0xffffffffu, f, __ffs(bal) - 1);
                    found = true;
                    break;
                }
            }
        }
        int cy, cx;
        if (found) {
            if (lane == 0) occ[chosen >> 5] |= 1u << (chosen & 31);
            cy = chosen / WW; cx = chosen - cy * WW;
        } else { cy = y0c; cx = x0c; }
        __syncwarp();
        if (lane == 0) {
            g_centi[(b * CC + c) * 2 + 0] = cy;
            g_centi[(b * CC + c) * 2 + 1] = cx;
            out_cents[(b * CC + c) * 2 + 0] = (float)cy;
            out_cents[(b * CC + c) * 2 + 1] = (float)cx;
        }
    }
}

// ---------------- Phase 2: maps + init (fused) ----------------
__global__ void maps_kernel(const float* __restrict__ xin, const float* __restrict__ g) {
    int i = blockIdx.x * blockDim.x + threadIdx.x;
    if (i >= BB * HWP) return;
    int b = i / HWP;
    int r = i - b * HWP;
    int y = r / WW;
    int x = r - y * WW;

    float gv = g[i];
    float t = gv * gv;
    g_wg[i] = (t * t) * 10.0f;

    const float* cb = xin + (size_t)b * 3 * HWP;
    int yn = (y + 1 == HH) ? 0 : y + 1;
    int xn = (x + 1 == WW) ? 0 : x + 1;
    int rU = yn * WW + x;
    int rL = y * WW + xn;
    float su = 0.0f, sl = 0.0f;
    #pragma unroll
    for (int ch = 0; ch < 3; ch++) {
        float v = cb[ch * HWP + r];
        su += fabsf(v - cb[ch * HWP + rU]);
        sl += fabsf(v - cb[ch * HWP + rL]);
    }
    g_cpU[i] = su * 10.0f;
    g_cpL[i] = sl * 10.0f;

    g_dA[i] = CUDART_INF_F;     // init fused here
    g_lA[i] = 255;
}

// Parallel seed: one thread per (b,c). Collision-free (round-9 analysis).
__global__ void seed_kernel() {
    int i = blockIdx.x * blockDim.x + threadIdx.x;
    if (i >= BB * CC) return;
    int y = g_centi[i * 2 + 0];
    int x = g_centi[i * 2 + 1];
    int b = i / CC;
    int idx = b * HWP + y * WW + x;
    g_dA[idx] = 0.0f;
    g_lA[idx] = (unsigned char)(i - b * CC);
}

// ---------------- packed-label helpers ----------------
__device__ __forceinline__ unsigned getb(const unsigned* lab, int q) {
    return (lab[q >> 2] >> ((q & 3) * 8)) & 0xFFu;
}
__device__ __forceinline__ void setb(unsigned* lab, int q, unsigned v) {
    int sh = (q & 3) * 8;
    lab[q >> 2] = (lab[q >> 2] & ~(0xFFu << sh)) | (v << sh);
}

// ---------------- Phase 3: KIT fused iterations, 2 barriers/iteration ----------------
// Thread (x,h): column x, tile rows [h*RPT, h*RPT+RPT). dist+labels in regs;
// wg/cpU/cpL tiles in dynamic smem. Barrier 1 ships pre-U seam values both
// ways; h=1 recomputes h=0's post-U row RPT-1 locally, so U and D run without
// an intervening barrier. Barrier 2 ships pre-L boundary values (lane 0 and
// lane 31); lane 0 recomputes its left neighbor's post-L value locally, so L
// and R run without an intervening barrier. All exchanges single-buffered
// (write/read pairs separated by barriers on both sides).
// Exact reference add order (nd+wg)+cp throughout.
template <bool LAST>
__global__ void __launch_bounds__(NT*NH, 2) fused_reg_kernel(int ab, float* __restrict__ out_mask) {
    extern __shared__ float s_dyn[];
    float* swg = s_dyn;                  // [TFY][NT]
    float* scU = s_dyn + TFY * NT;
    float* scL = s_dyn + 2 * TFY * NT;

    __shared__ float    sLd[NH][NW][RPT];   // lane-0 pre-L state
    __shared__ unsigned sLl[NH][NW][NLAB];
    __shared__ float    sRd[NH][NW][RPT];   // lane-31 pre-L state
    __shared__ unsigned sRl[NH][NW][NLAB];
    __shared__ float    seamUd[NT];         // h=1 row0 pre-U
    __shared__ unsigned seamUl[NT];
    __shared__ float    seamDd[NT];         // h=0 row RPT-1 pre-U
    __shared__ unsigned seamDl[NT];

    const float*         din  = ab ? g_dB : g_dA;
    float*               dout = ab ? g_dA : g_dB;
    const unsigned char* lin  = ab ? g_lB : g_lA;
    unsigned char*       lout = ab ? g_lA : g_lB;

    const int x    = threadIdx.x;
    const int h    = threadIdx.y;
    const int lane = x & 31;
    const int wq   = x >> 5;
    const int wqn  = (wq + 1) % NW;
    const int wqp  = (wq + NW - 1) % NW;
    const int xl   = (x == 0) ? WW - 1 : x - 1;
    const int band = blockIdx.x;
    const int b    = blockIdx.y;
    const int bb   = b * HWP;
    const int y0   = band * BR - KIT;
    const int tb   = h * RPT;

    float    dist[RPT];
    unsigned lab[NLAB];

    // ---- load (coalesced) ----
    #pragma unroll
    for (int rl = 0; rl < RPT; rl++) {
        int t  = tb + rl;
        int gy = y0 + t; if (gy < 0) gy += HH; else if (gy >= HH) gy -= HH;
        int gi = bb + gy * WW + x;
        dist[rl]      = din[gi];
        swg[t*NT + x] = g_wg [gi];
        scU[t*NT + x] = g_cpU[gi];
        scL[t*NT + x] = g_cpL[gi];
        unsigned lv = lin[gi];
        if ((rl & 3) == 0) lab[rl >> 2] = lv;
        else               lab[rl >> 2] |= lv << ((rl & 3) * 8);
    }
    // First cross-thread smem reads happen after the first __syncthreads (B1).

    for (int i = 0; i < KIT; i++) {
        // ---- B1: pre-U seam exchange (both directions) ----
        float preU19d = 0.0f; unsigned preU19l = 0u;
        if (h == 1) {
            preU19d = dist[0]; preU19l = getb(lab, 0);
            seamUd[x] = preU19d; seamUl[x] = preU19l;
        } else {
            seamDd[x] = dist[RPT - 1]; seamDl[x] = getb(lab, RPT - 1);
        }
        __syncthreads();

        if (h == 0) {
            // ---- U: rl in [i, RPT-1], ascending ----
            #pragma unroll
            for (int rl = 0; rl < RPT; rl++) {
                if (rl >= i) {
                    float nd; unsigned nl;
                    if (rl < RPT - 1) { nd = dist[rl + 1]; nl = getb(lab, rl + 1); }
                    else              { nd = seamUd[x];    nl = seamUl[x]; }
                    float wd = (nd + swg[rl*NT + x]) + scU[rl*NT + x];
                    if (wd < dist[rl]) { dist[rl] = wd; setb(lab, rl, nl); }
                }
            }
            // ---- D: rl in [i+1, RPT-1], descending (all internal) ----
            #pragma unroll
            for (int rr = 0; rr < RPT - 1; rr++) {
                int rl = RPT - 1 - rr;
                if (rl >= i + 1) {
                    float wd = (dist[rl - 1] + swg[rl*NT + x]) + scU[(rl-1)*NT + x];
                    if (wd < dist[rl]) { dist[rl] = wd; setb(lab, rl, getb(lab, rl - 1)); }
                }
            }
        } else {
            // ---- U: rl in [0, RPT-1-i) ----
            #pragma unroll
            for (int rl = 0; rl < RPT - 1; rl++) {
                if (rl < RPT - 1 - i) {
                    int t = RPT + rl;
                    float wd = (dist[rl + 1] + swg[t*NT + x]) + scU[t*NT + x];
                    if (wd < dist[rl]) { dist[rl] = wd; setb(lab, rl, getb(lab, rl + 1)); }
                }
            }
            // ---- recompute h=0's post-U row RPT-1 (t=18: always in U window) ----
            float o18 = seamDd[x]; unsigned l18 = seamDl[x];
            {
                float wd = (preU19d + swg[(RPT-1)*NT + x]) + scU[(RPT-1)*NT + x];
                if (wd < o18) { o18 = wd; l18 = preU19l; }
            }
            // ---- D: rl in [0, RPT-1-i), descending ----
            #pragma unroll
            for (int rr = 0; rr < RPT; rr++) {
                int rl = RPT - 1 - rr;
                if (rl < RPT - 1 - i) {
                    int t = RPT + rl;
                    float nd; unsigned nl;
                    if (rl > 0) { nd = dist[rl - 1]; nl = getb(lab, rl - 1); }
                    else        { nd = o18;          nl = l18; }
                    float wd = (nd + swg[t*NT + x]) + scU[(t-1)*NT + x];
                    if (wd < dist[rl]) { dist[rl] = wd; setb(lab, rl, nl); }
                }
            }
        }

        // ---- B2: pre-L boundary exchange (lane 0 AND lane 31) ----
        if (lane == 0) {
            #pragma unroll
            for (int rl = 0; rl < RPT; rl++) sLd[h][wq][rl] = dist[rl];
            #pragma unroll
            for (int k = 0; k < NLAB; k++)   sLl[h][wq][k] = lab[k];
        }
        if (lane == 31) {
            #pragma unroll
            for (int rl = 0; rl < RPT; rl++) sRd[h][wq][rl] = dist[rl];
            #pragma unroll
            for (int k = 0; k < NLAB; k++)   sRl[h][wq][k] = lab[k];
        }
        __syncthreads();

        // ---- L: reads column x+1 (pre-L) ----
        {
            unsigned nlab[NLAB];
            #pragma unroll
            for (int k = 0; k < NLAB; k++) {
                nlab[k] = __shfl_down_sync(0xffffffffu, lab[k], 1);
                if (lane == 31) nlab[k] = sLl[h][wqn][k];
            }
            #pragma unroll
            for (int rl = 0; rl < RPT; rl++) {
                float nd = __shfl_down_sync(0xffffffffu, dist[rl], 1);
                bool act = (h == 0) ? (rl >= i + 1) : (rl < RPT - 1 - i);
                if (act) {
                    if (lane == 31) nd = sLd[h][wqn][rl];
                    int t = tb + rl;
                    float wd = (nd + swg[t*NT + x]) + scL[t*NT + x];
                    if (wd < dist[rl]) { dist[rl] = wd; setb(lab, rl, getb(nlab, rl)); }
                }
            }
        }
        // ---- R: reads column x-1 (post-L); lane 0 recomputes boundary ----
        {
            unsigned nlab[NLAB];
            #pragma unroll
            for (int k = 0; k < NLAB; k++)
                nlab[k] = __shfl_up_sync(0xffffffffu, lab[k], 1);
            #pragma unroll
            for (int rl = 0; rl < RPT; rl++) {
                float nd = __shfl_up_sync(0xffffffffu, dist[rl], 1);
                bool act = (h == 0) ? (rl >= i + 1) : (rl < RPT - 1 - i);
                if (act) {
                    unsigned nl = getb(nlab, rl);
                    int t = tb + rl;
                    if (lane == 0) {
                        // postL(xl) = L-update(preL(xl), preL(x), maps(xl))
                        float    pnb   = sRd[h][wqp][rl];
                        unsigned lnb   = (sRl[h][wqp][rl >> 2] >> ((rl & 3) * 8)) & 0xFFu;
                        float    pself = sLd[h][wq][rl];
                        unsigned lself = (sLl[h][wq][rl >> 2] >> ((rl & 3) * 8)) & 0xFFu;
                        float wd2 = (pself + swg[t*NT + xl]) + scL[t*NT + xl];
                        if (wd2 < pnb) { nd = wd2; nl = lself; }
                        else           { nd = pnb; nl = lnb; }
                    }
                    float wd = (nd + swg[t*NT + x]) + scL[t*NT + xl];
                    if (wd < dist[rl]) { dist[rl] = wd; setb(lab, rl, nl); }
                }
            }
        }
    }

    // ---- store interior tile rows [KIT, KIT+BR) ----
    if (h == 0) {
        #pragma unroll
        for (int rl = KIT; rl < RPT; rl++) {
            int gi = bb + (band * BR + rl - KIT) * WW + x;
            unsigned v = getb(lab, rl);
            if (LAST) out_mask[gi] = (v == 255u) ? -1.0f : (float)v;
            else      { dout[gi] = dist[rl]; lout[gi] = (unsigned char)v; }
        }
    } else {
        #pragma unroll
        for (int rl = 0; rl < BR - (RPT - KIT); rl++) {
            int gi = bb + (band * BR + (RPT - KIT) + rl) * WW + x;
            unsigned v = getb(lab, rl);
            if (LAST) out_mask[gi] = (v == 255u) ? -1.0f : (float)v;
            else      { dout[gi] = dist[rl]; lout[gi] = (unsigned char)v; }
        }
    }
}

// ---------------- launch ----------------
extern "C" void kernel_launch(void* const* d_in, const int* in_sizes, int n_in,
                              void* d_out, int out_size) {
    const float* x;
    const float* g;
    if (in_sizes[0] == BB * 3 * HWP) { x = (const float*)d_in[0]; g = (const float*)d_in[1]; }
    else                             { x = (const float*)d_in[1]; g = (const float*)d_in[0]; }

    float* out       = (float*)d_out;
    float* out_cents = out;               // [B, C, 2] float32
    float* out_mask  = out + BB * CC * 2; // [B, H, W] float32

    const int NPX = BB * HWP;
    const int TPB = 256;
    const int GPX = (NPX + TPB - 1) / TPB;

    cudaFuncSetAttribute(fused_reg_kernel<false>,
                         cudaFuncAttributeMaxDynamicSharedMemorySize, DYN_SMEM);
    cudaFuncSetAttribute(fused_reg_kernel<true>,
                         cudaFuncAttributeMaxDynamicSharedMemorySize, DYN_SMEM);

    minima_kernel<<<(BB * CC * 32 + TPB - 1) / TPB, TPB>>>(g);
    resolve_kernel<<<BB, 32>>>(g, out_cents);
    maps_kernel<<<GPX, TPB>>>(x, g);
    seed_kernel<<<(BB * CC + TPB - 1) / TPB, TPB>>>();

    dim3 blk(NT, NH);
    int ab = 0;   // 0: current state in A
    const int NLAUNCH = 50 / KIT;   // 10
    for (int k = 0; k < NLAUNCH - 1; k++) {
        fused_reg_kernel<false><<<dim3(BANDS, BB), blk, DYN_SMEM>>>(ab, out_mask);
        ab ^= 1;
    }
    fused_reg_kernel<true><<<dim3(BANDS, BB), blk, DYN_SMEM>>>(ab, out_mask);
}